// round 14
// baseline (speedup 1.0000x reference)
#include <cuda_runtime.h>

// BillehColumn GLIF3 simulation, forward only.
// Round 14: spike-LIST communication instead of global rec buffers.
// Spiking neurons publish (id,count) to a per-step global list; at step
// start every block scans the (few) spikers' synapse buckets and accumulates
// weights for its own neurons into SMEM. Neuron input gather becomes an LDS;
// the 400k-slot global rec buffers, their L2 round-trips, and all global
// scatter atomics are gone. Barrier skeleton = R11 (proven best).

#define Nn 100000
#define Rr 4
#define Ee 2000000
#define Tt 50
#define NRr (Nn * Rr)
#define SS 64                 // synapse slots per pre-neuron
#define OVF_CAP 4096
#define TPB 704               // 22 warps
#define NW (TPB / 32)
#define GRID 148              // 148 x 704 = 104192 >= N, one block per SM
#define SLOTS (TPB * Rr)      // smem rec slots per block

__device__ int   g_cnt[Nn];
__device__ int   g_ovf_cnt;
__device__ int   g_bar;
__device__ int   g_spk_n[Tt + 1];            // spike count consumed at step t
__device__ int   g_spk_list[(Tt + 1) * Nn];  // packed (n<<7)|min(cnt,127)
__device__ int2  g_syn[Nn * SS];             // {target slot, weight bits}
__device__ int   g_ovf_pre[OVF_CAP];
__device__ int   g_ovf_tgt[OVF_CAP];
__device__ float g_ovf_w[OVF_CAP];

__device__ __forceinline__ void bar_arrive_release() {
    asm volatile("red.release.gpu.global.add.s32 [%0], 1;"
                 :: "l"(&g_bar) : "memory");
}
__device__ __forceinline__ int bar_read_acquire() {
    int v;
    asm volatile("ld.acquire.gpu.global.s32 %0, [%1];"
                 : "=r"(v) : "l"(&g_bar) : "memory");
    return v;
}

// ---------------------------------------------------------------------------
// Zero counts, spike counters, barrier state.
__global__ void k_zero() {
    int i = blockIdx.x * blockDim.x + threadIdx.x;
    int stride = gridDim.x * blockDim.x;
    for (int j = i; j < Nn; j += stride)
        g_cnt[j] = 0;
    if (i <= Tt) g_spk_n[i] = 0;
    if (i == 0) { g_ovf_cnt = 0; g_bar = 0; }
}

// ---------------------------------------------------------------------------
// Single-pass synapse bucketing: slot = pre*SS + running count.
__global__ void k_fill(const int* __restrict__ pre,
                       const int* __restrict__ post,
                       const int* __restrict__ rcp,
                       const float* __restrict__ w) {
    int i = blockIdx.x * blockDim.x + threadIdx.x;   // quad index
    if (i >= Ee / 4) return;
    int4 p4 = ((const int4*)pre)[i];
    int4 q4 = ((const int4*)post)[i];
    int4 r4 = ((const int4*)rcp)[i];
    float4 w4 = ((const float4*)w)[i];

    int   ps[4] = {p4.x, p4.y, p4.z, p4.w};
    int   ts[4] = {q4.x * Rr + r4.x, q4.y * Rr + r4.y,
                   q4.z * Rr + r4.z, q4.w * Rr + r4.w};
    float ws[4] = {w4.x, w4.y, w4.z, w4.w};

#pragma unroll
    for (int k = 0; k < 4; k++) {
        int p = ps[k];
        int c = atomicAdd(&g_cnt[p], 1);
        if (c < SS) {
            g_syn[p * SS + c] = make_int2(ts[k], __float_as_int(ws[k]));
        } else {
            int o = atomicAdd(&g_ovf_cnt, 1);
            if (o < OVF_CAP) {
                g_ovf_pre[o] = p;
                g_ovf_tgt[o] = ts[k];
                g_ovf_w[o] = ws[k];
            }
        }
    }
}

// ---------------------------------------------------------------------------
// Persistent simulation. One thread per neuron; all state in registers.
__global__ void __launch_bounds__(TPB, 1) k_sim(
    const float* __restrict__ x_ext,
    float* __restrict__ out,
    const float* __restrict__ v0,
    const float* __restrict__ vth_,
    const float* __restrict__ vreset_,
    const float* __restrict__ tref_,
    const float* __restrict__ decay_,
    const float* __restrict__ cf_,
    const float* __restrict__ el_,
    const float* __restrict__ amps_,
    const float* __restrict__ ascd_,
    const float* __restrict__ syn_decay,
    const float* __restrict__ psc_init)
{
    __shared__ float srec[SLOTS];      // block-local rec accumulators
    __shared__ int s_done[2];          // parity warp-arrival counters

    const int n = blockIdx.x * TPB + threadIdx.x;
    const bool act = (n < Nn);
    const int wid = threadIdx.x >> 5;
    const int lane = threadIdx.x & 31;
    const int lo = blockIdx.x * SLOTS; // first rec slot owned by this block

    const float4 sd = *(const float4*)syn_decay;
    const float4 pi = *(const float4*)psc_init;

    // Register-resident state.
    float v = 0.f, r = 0.f, z = 0.f;
    float2 a = make_float2(0.f, 0.f);
    float4 psc = make_float4(0.f, 0.f, 0.f, 0.f);
    float4 pr  = make_float4(0.f, 0.f, 0.f, 0.f);
    // Register-resident params.
    float vth = 1.f, inv_vth = 1.f, rst = 0.f, trf = 0.f;
    float dec = 0.f, cf = 0.f, el = 0.f;
    float2 am = make_float2(0.f, 0.f), ad = make_float2(0.f, 0.f);
    int sc = 0;
    float4 x = make_float4(0.f, 0.f, 0.f, 0.f);

    if (act) {
        v   = v0[n];
        vth = vth_[n];
        inv_vth = 1.f / vth;
        rst = vreset_[n] - vth;
        trf = tref_[n];
        dec = decay_[n];
        cf  = cf_[n];
        el  = el_[n];
        am  = *(const float2*)(&amps_[2 * n]);
        ad  = *(const float2*)(&ascd_[2 * n]);
        sc  = g_cnt[n];
        x   = __ldcs((const float4*)x_ext + n);   // step 0 input
    }
    const int my_pack = (n << 7) | (sc < 127 ? sc : 127);

    // Zero smem rec and barrier state.
    for (int i = threadIdx.x; i < SLOTS; i += TPB) srec[i] = 0.f;
    if (threadIdx.x == 0) { s_done[0] = 0; s_done[1] = 0; }
    __syncthreads();

    for (int t = 0; t < Tt; t++) {
        const int p = t & 1;

        // ---- Phase 1: apply incoming spikes (list produced at step t-1). ----
        const int S = __ldcg(&g_spk_n[t]);
        if (S > 0) {
            const int* list_t = g_spk_list + (size_t)t * Nn;
            for (int i = wid; i < S; i += NW) {
                int packed = __ldcg(&list_t[i]);   // broadcast within warp
                int nn = packed >> 7;
                int mm = packed & 127;
                int m1 = (mm < SS) ? mm : SS;
                int base = nn * SS;
                for (int s = lane; s < m1; s += 32) {
                    int2 e = g_syn[base + s];
                    unsigned rel = (unsigned)(e.x - lo);
                    if (rel < (unsigned)SLOTS)
                        atomicAdd(&srec[rel], __int_as_float(e.y));
                }
                if (mm > SS) {  // overflow entries (practically never)
                    int oc = g_ovf_cnt;
                    if (oc > OVF_CAP) oc = OVF_CAP;
                    for (int o = lane; o < oc; o += 32) {
                        if (g_ovf_pre[o] == nn) {
                            unsigned rel = (unsigned)(g_ovf_tgt[o] - lo);
                            if (rel < (unsigned)SLOTS)
                                atomicAdd(&srec[rel], g_ovf_w[o]);
                        }
                    }
                }
            }
        }
        __syncthreads();   // Sync A: srec complete

        // ---- Phase 2: neuron update (inputs from SMEM). ----
        float zn = 0.f;
        if (act) {
            const int si = threadIdx.x * 4;
            float4 rec = *(float4*)&srec[si];
            *(float4*)&srec[si] = make_float4(0.f, 0.f, 0.f, 0.f);

            float in0 = rec.x + x.x;
            float in1 = rec.y + x.y;
            float in2 = rec.z + x.z;
            float in3 = rec.w + x.w;

            // Prefetch next step's external input (hidden behind the barrier).
            if (t + 1 < Tt)
                x = __ldcs((const float4*)x_ext + (size_t)(t + 1) * Nn + n);

            float4 npr, npsc;
            npr.x = pr.x * sd.x + in0 * pi.x;
            npr.y = pr.y * sd.y + in1 * pi.y;
            npr.z = pr.z * sd.z + in2 * pi.z;
            npr.w = pr.w * sd.w + in3 * pi.w;
            npsc.x = psc.x * sd.x + sd.x * pr.x;
            npsc.y = psc.y * sd.y + sd.y * pr.y;
            npsc.z = psc.z * sd.z + sd.z * pr.z;
            npsc.w = psc.w * sd.w + sd.w * pr.w;
            psc = npsc;
            pr = npr;

            float psum = ((npsc.x + npsc.y) + npsc.z) + npsc.w;
            float input_current = psum + (a.x + a.y);   // OLD asc

            a.x = ad.x * a.x + z * am.x;
            a.y = ad.y * a.y + z * am.y;

            float nv = dec * v + cf * (input_current + el) + z * rst;
            float vsc = (nv - vth) * inv_vth;

            zn = (vsc > 0.f) ? 1.f : 0.f;
            if (r > 0.f) zn = 0.f;
            r = fmaxf(r - 1.f + zn * trf, 0.f);
            v = nv;
            z = zn;

            __stcs(&out[(size_t)t * Nn + n], zn);

            // ---- Phase 3: publish spike to next step's global list. ----
            if (zn != 0.f && t + 1 < Tt) {
                int idx = atomicAdd(&g_spk_n[t + 1], 1);
                g_spk_list[(size_t)(t + 1) * Nn + idx] = my_pack;
                __threadfence();   // entry visible before our barrier arrive
            }
        }

        // ---- Grid barrier (skip after final step). ----
        if (t + 1 < Tt) {
            __syncwarp();
            if (lane == 0) {
                int d = atomicAdd(&s_done[p], 1);
                if (d == NW - 1) {
                    s_done[p] = 0;             // reset for step t+2 (parity)
                    bar_arrive_release();      // release: block complete
                }
            }
            if (threadIdx.x == 0) {
                const int target = GRID * (t + 1);
                while (bar_read_acquire() < target) { }
            }
            __syncthreads();   // Sync B: all warps wait for the poll
        }
    }
}

// ---------------------------------------------------------------------------
extern "C" void kernel_launch(void* const* d_in, const int* in_sizes, int n_in,
                              void* d_out, int out_size) {
    const float* w_rec     = (const float*)d_in[0];
    const float* x_ext     = (const float*)d_in[1];
    const float* v0        = (const float*)d_in[2];
    const float* vth       = (const float*)d_in[3];
    const float* vreset    = (const float*)d_in[4];
    const float* tref      = (const float*)d_in[5];
    const float* decay     = (const float*)d_in[6];
    const float* cf        = (const float*)d_in[7];
    const float* el        = (const float*)d_in[8];
    const float* amps      = (const float*)d_in[9];
    const float* ascd      = (const float*)d_in[10];
    const float* syn_decay = (const float*)d_in[11];
    const float* psc_init  = (const float*)d_in[12];
    const int*   pre       = (const int*)d_in[13];
    const int*   post      = (const int*)d_in[14];
    const int*   rcp       = (const int*)d_in[15];
    float* out = (float*)d_out;

    k_zero<<<394, 256>>>();
    k_fill<<<(Ee / 4 + 255) / 256, 256>>>(pre, post, rcp, w_rec);
    k_sim<<<GRID, TPB>>>(x_ext, out, v0, vth, vreset, tref, decay, cf, el,
                         amps, ascd, syn_decay, psc_init);
}

// round 15
// speedup vs baseline: 30.3803x; 30.3803x over previous
#include <cuda_runtime.h>

// BillehColumn GLIF3 simulation, forward only.
// Round 15: R11 base (best @246us: block scatter queue, conditional
// zero-store, 148-arriver GPU-scope RED barrier) with:
//  - named-barrier block completion (removes the 22-warp smem ATOMS chain
//    from the critical path; the good half of R12, without its bad scatter)
//  - packed queue entries (n<<7|m): one STS instead of two
//  - slimmer prep: rec zeroing folded into k_fill, 8 synapses/thread

#define Nn 100000
#define Rr 4
#define Ee 2000000
#define Tt 50
#define NRr (Nn * Rr)
#define SS 64                 // synapse slots per pre-neuron
#define OVF_CAP 4096
#define TPB 704               // 22 warps
#define NW (TPB / 32)
#define GRID 148              // 148 x 704 = 104192 >= N, one block per SM

__device__ float g_rec[2][NRr];
__device__ int   g_cnt[Nn];
__device__ int   g_ovf_cnt;
__device__ int   g_bar;
__device__ int2  g_syn[Nn * SS];       // {target slot, weight bits}
__device__ int   g_ovf_pre[OVF_CAP];
__device__ int   g_ovf_tgt[OVF_CAP];
__device__ float g_ovf_w[OVF_CAP];

__device__ __forceinline__ void bar_arrive_release() {
    asm volatile("red.release.gpu.global.add.s32 [%0], 1;"
                 :: "l"(&g_bar) : "memory");
}
__device__ __forceinline__ int bar_read_acquire() {
    int v;
    asm volatile("ld.acquire.gpu.global.s32 %0, [%1];"
                 : "=r"(v) : "l"(&g_bar) : "memory");
    return v;
}

// ---------------------------------------------------------------------------
// Zero counts + scalars (rec zeroing lives in k_fill's prologue).
__global__ void k_zero() {
    int i = blockIdx.x * blockDim.x + threadIdx.x;
    int stride = gridDim.x * blockDim.x;
    for (int j = i; j < Nn; j += stride)
        g_cnt[j] = 0;
    if (i == 0) { g_ovf_cnt = 0; g_bar = 0; }
}

// ---------------------------------------------------------------------------
// Zero rec buffers (no dependency on counts), then single-pass synapse
// bucketing: slot = pre*SS + running count. 8 synapses per thread.
__global__ void k_fill(const int* __restrict__ pre,
                       const int* __restrict__ post,
                       const int* __restrict__ rcp,
                       const float* __restrict__ w) {
    int i = blockIdx.x * blockDim.x + threadIdx.x;   // octet index
    int nthreads = gridDim.x * blockDim.x;

    // Prologue: zero both rec buffers (grid covers it in one stride pass).
    float4* r4 = (float4*)g_rec;
    for (int j = i; j < (2 * NRr) / 4; j += nthreads)
        r4[j] = make_float4(0.f, 0.f, 0.f, 0.f);

    if (i >= Ee / 8) return;

#pragma unroll
    for (int half = 0; half < 2; half++) {
        int q = 2 * i + half;                         // quad index
        int4 p4 = ((const int4*)pre)[q];
        int4 q4 = ((const int4*)post)[q];
        int4 r4i = ((const int4*)rcp)[q];
        float4 w4 = ((const float4*)w)[q];

        int   ps[4] = {p4.x, p4.y, p4.z, p4.w};
        int   ts[4] = {q4.x * Rr + r4i.x, q4.y * Rr + r4i.y,
                       q4.z * Rr + r4i.z, q4.w * Rr + r4i.w};
        float ws[4] = {w4.x, w4.y, w4.z, w4.w};

#pragma unroll
        for (int k = 0; k < 4; k++) {
            int p = ps[k];
            int c = atomicAdd(&g_cnt[p], 1);
            if (c < SS) {
                g_syn[p * SS + c] = make_int2(ts[k], __float_as_int(ws[k]));
            } else {
                int o = atomicAdd(&g_ovf_cnt, 1);
                if (o < OVF_CAP) {
                    g_ovf_pre[o] = p;
                    g_ovf_tgt[o] = ts[k];
                    g_ovf_w[o] = ws[k];
                }
            }
        }
    }
}

// ---------------------------------------------------------------------------
// Persistent simulation. One thread per neuron; all state in registers.
__global__ void __launch_bounds__(TPB, 1) k_sim(
    const float* __restrict__ x_ext,
    float* __restrict__ out,
    const float* __restrict__ v0,
    const float* __restrict__ vth_,
    const float* __restrict__ vreset_,
    const float* __restrict__ tref_,
    const float* __restrict__ decay_,
    const float* __restrict__ cf_,
    const float* __restrict__ el_,
    const float* __restrict__ amps_,
    const float* __restrict__ ascd_,
    const float* __restrict__ syn_decay,
    const float* __restrict__ psc_init)
{
    __shared__ int q_ent[TPB];         // packed (n<<7 | m)
    __shared__ int q_n2[2];            // parity queue counters

    const int n = blockIdx.x * TPB + threadIdx.x;
    const bool act = (n < Nn);
    const int wid = threadIdx.x >> 5;
    const int lane = threadIdx.x & 31;

    const float4 sd = *(const float4*)syn_decay;
    const float4 pi = *(const float4*)psc_init;

    // Register-resident state.
    float v = 0.f, r = 0.f, z = 0.f;
    float2 a = make_float2(0.f, 0.f);
    float4 psc = make_float4(0.f, 0.f, 0.f, 0.f);
    float4 pr  = make_float4(0.f, 0.f, 0.f, 0.f);
    // Register-resident params.
    float vth = 1.f, inv_vth = 1.f, rst = 0.f, trf = 0.f;
    float dec = 0.f, cf = 0.f, el = 0.f;
    float2 am = make_float2(0.f, 0.f), ad = make_float2(0.f, 0.f);
    int sc = 0;
    float4 x = make_float4(0.f, 0.f, 0.f, 0.f);

    if (act) {
        v   = v0[n];
        vth = vth_[n];
        inv_vth = 1.f / vth;
        rst = vreset_[n] - vth;
        trf = tref_[n];
        dec = decay_[n];
        cf  = cf_[n];
        el  = el_[n];
        am  = *(const float2*)(&amps_[2 * n]);
        ad  = *(const float2*)(&ascd_[2 * n]);
        sc  = g_cnt[n];
        x   = __ldcs((const float4*)x_ext + n);   // step 0 input
    }
    const int m_syn = act ? ((sc < SS) ? sc : SS) : 0;
    const int my_pack = (n << 7) | m_syn;          // m_syn <= 64 fits 7 bits

    if (threadIdx.x == 0) { q_n2[0] = 0; q_n2[1] = 0; }
    __syncthreads();

    for (int t = 0; t < Tt; t++) {
        const int p = t & 1;
        float* rec_cur = g_rec[p];
        float* rec_nxt = g_rec[p ^ 1];

        float zn = 0.f;
        if (act) {
            // L2-coherent read of this neuron's rec slots; zero only if dirty.
            float4 rec = __ldcg((const float4*)(rec_cur + 4 * n));
            if (rec.x != 0.f || rec.y != 0.f || rec.z != 0.f || rec.w != 0.f)
                __stcg((float4*)(rec_cur + 4 * n),
                       make_float4(0.f, 0.f, 0.f, 0.f));

            float in0 = rec.x + x.x;
            float in1 = rec.y + x.y;
            float in2 = rec.z + x.z;
            float in3 = rec.w + x.w;

            // Prefetch next step's external input (hidden behind the barrier).
            if (t + 1 < Tt)
                x = __ldcs((const float4*)x_ext + (size_t)(t + 1) * Nn + n);

            float4 npr, npsc;
            npr.x = pr.x * sd.x + in0 * pi.x;
            npr.y = pr.y * sd.y + in1 * pi.y;
            npr.z = pr.z * sd.z + in2 * pi.z;
            npr.w = pr.w * sd.w + in3 * pi.w;
            npsc.x = psc.x * sd.x + sd.x * pr.x;
            npsc.y = psc.y * sd.y + sd.y * pr.y;
            npsc.z = psc.z * sd.z + sd.z * pr.z;
            npsc.w = psc.w * sd.w + sd.w * pr.w;
            psc = npsc;
            pr = npr;

            float psum = ((npsc.x + npsc.y) + npsc.z) + npsc.w;
            float input_current = psum + (a.x + a.y);   // OLD asc

            a.x = ad.x * a.x + z * am.x;
            a.y = ad.y * a.y + z * am.y;

            float nv = dec * v + cf * (input_current + el) + z * rst;
            float vsc = (nv - vth) * inv_vth;

            zn = (vsc > 0.f) ? 1.f : 0.f;
            if (r > 0.f) zn = 0.f;
            r = fmaxf(r - 1.f + zn * trf, 0.f);
            v = nv;
            z = zn;

            __stcs(&out[(size_t)t * Nn + n], zn);

            // Publish spike into the block scatter queue (packed entry).
            if (zn != 0.f) {
                int idx = atomicAdd(&q_n2[p], 1);
                q_ent[idx] = my_pack;
            }
        }

        // Sync A: queue visible to all warps.
        __syncthreads();

        // Reset opposite-parity queue counter for step t+1.
        if (threadIdx.x == 0) q_n2[p ^ 1] = 0;

        // Block-cooperative scatter: warps round-robin over queue entries.
        {
            const int total = q_n2[p];
            for (int i = wid; i < total; i += NW) {
                int e = q_ent[i];
                int b = (e >> 7) * SS;
                int m = e & 127;
                for (int s = lane; s < m; s += 32) {
                    int2 rec2 = g_syn[b + s];
                    atomicAdd(&rec_nxt[rec2.x], __int_as_float(rec2.y));
                }
            }
            // Overflow entries (practically never taken).
            if (zn != 0.f && sc > SS) {
                int oc = g_ovf_cnt;
                if (oc > OVF_CAP) oc = OVF_CAP;
                for (int o = 0; o < oc; o++) {
                    if (g_ovf_pre[o] == n)
                        atomicAdd(&rec_nxt[g_ovf_tgt[o]], g_ovf_w[o]);
                }
            }
        }

        // Grid barrier (skip after final step). Warps 1..21 signal completion
        // via non-blocking named-barrier arrive; warp 0 collects them, fires
        // the block's single global RED arrive, and polls.
        if (t + 1 < Tt) {
            if (wid != 0) {
                asm volatile("bar.arrive 1, %0;" :: "r"(TPB) : "memory");
            } else {
                asm volatile("bar.sync 1, %0;" :: "r"(TPB) : "memory");
                if (lane == 0) {
                    bar_arrive_release();      // release: block's scatters
                    const int target = GRID * (t + 1);
                    while (bar_read_acquire() < target) { }
                }
            }
            // Sync B: all warps wait for warp 0's poll to pass.
            __syncthreads();
        }
    }
}

// ---------------------------------------------------------------------------
extern "C" void kernel_launch(void* const* d_in, const int* in_sizes, int n_in,
                              void* d_out, int out_size) {
    const float* w_rec     = (const float*)d_in[0];
    const float* x_ext     = (const float*)d_in[1];
    const float* v0        = (const float*)d_in[2];
    const float* vth       = (const float*)d_in[3];
    const float* vreset    = (const float*)d_in[4];
    const float* tref      = (const float*)d_in[5];
    const float* decay     = (const float*)d_in[6];
    const float* cf        = (const float*)d_in[7];
    const float* el        = (const float*)d_in[8];
    const float* amps      = (const float*)d_in[9];
    const float* ascd      = (const float*)d_in[10];
    const float* syn_decay = (const float*)d_in[11];
    const float* psc_init  = (const float*)d_in[12];
    const int*   pre       = (const int*)d_in[13];
    const int*   post      = (const int*)d_in[14];
    const int*   rcp       = (const int*)d_in[15];
    float* out = (float*)d_out;

    k_zero<<<392, 256>>>();
    k_fill<<<(Ee / 8 + 255) / 256, 256>>>(pre, post, rcp, w_rec);
    k_sim<<<GRID, TPB>>>(x_ext, out, v0, vth, vreset, tref, decay, cf, el,
                         amps, ascd, syn_decay, psc_init);
}

// round 16
// speedup vs baseline: 32.5864x; 1.0726x over previous
#include <cuda_runtime.h>

// BillehColumn GLIF3 simulation, forward only.
// Round 16: R15 base (best @237.8us) with the step DATAFLOW reordered.
// Key insight: input_current depends only on last step's psc/psc_rise (the
// rec input feeds psc_rise, which reaches the voltage two steps later), so
// the spike decision needs NO rec load. The rec load is issued at the top of
// the step and consumed only after publish+scatter — its L2 latency is fully
// hidden off the critical path. Arithmetic is unchanged (same ops, order).

#define Nn 100000
#define Rr 4
#define Ee 2000000
#define Tt 50
#define NRr (Nn * Rr)
#define SS 64                 // synapse slots per pre-neuron
#define OVF_CAP 4096
#define TPB 704               // 22 warps
#define NW (TPB / 32)
#define GRID 148              // 148 x 704 = 104192 >= N, one block per SM

__device__ float g_rec[2][NRr];
__device__ int   g_cnt[Nn];
__device__ int   g_ovf_cnt;
__device__ int   g_bar;
__device__ int2  g_syn[Nn * SS];       // {target slot, weight bits}
__device__ int   g_ovf_pre[OVF_CAP];
__device__ int   g_ovf_tgt[OVF_CAP];
__device__ float g_ovf_w[OVF_CAP];

__device__ __forceinline__ void bar_arrive_release() {
    asm volatile("red.release.gpu.global.add.s32 [%0], 1;"
                 :: "l"(&g_bar) : "memory");
}
__device__ __forceinline__ int bar_read_acquire() {
    int v;
    asm volatile("ld.acquire.gpu.global.s32 %0, [%1];"
                 : "=r"(v) : "l"(&g_bar) : "memory");
    return v;
}

// ---------------------------------------------------------------------------
// Zero counts + scalars (rec zeroing lives in k_fill's prologue).
__global__ void k_zero() {
    int i = blockIdx.x * blockDim.x + threadIdx.x;
    int stride = gridDim.x * blockDim.x;
    for (int j = i; j < Nn; j += stride)
        g_cnt[j] = 0;
    if (i == 0) { g_ovf_cnt = 0; g_bar = 0; }
}

// ---------------------------------------------------------------------------
// Zero rec buffers, then single-pass synapse bucketing. 8 synapses/thread.
__global__ void k_fill(const int* __restrict__ pre,
                       const int* __restrict__ post,
                       const int* __restrict__ rcp,
                       const float* __restrict__ w) {
    int i = blockIdx.x * blockDim.x + threadIdx.x;   // octet index
    int nthreads = gridDim.x * blockDim.x;

    float4* r4 = (float4*)g_rec;
    for (int j = i; j < (2 * NRr) / 4; j += nthreads)
        r4[j] = make_float4(0.f, 0.f, 0.f, 0.f);

    if (i >= Ee / 8) return;

#pragma unroll
    for (int half = 0; half < 2; half++) {
        int q = 2 * i + half;                         // quad index
        int4 p4 = ((const int4*)pre)[q];
        int4 q4 = ((const int4*)post)[q];
        int4 r4i = ((const int4*)rcp)[q];
        float4 w4 = ((const float4*)w)[q];

        int   ps[4] = {p4.x, p4.y, p4.z, p4.w};
        int   ts[4] = {q4.x * Rr + r4i.x, q4.y * Rr + r4i.y,
                       q4.z * Rr + r4i.z, q4.w * Rr + r4i.w};
        float ws[4] = {w4.x, w4.y, w4.z, w4.w};

#pragma unroll
        for (int k = 0; k < 4; k++) {
            int p = ps[k];
            int c = atomicAdd(&g_cnt[p], 1);
            if (c < SS) {
                g_syn[p * SS + c] = make_int2(ts[k], __float_as_int(ws[k]));
            } else {
                int o = atomicAdd(&g_ovf_cnt, 1);
                if (o < OVF_CAP) {
                    g_ovf_pre[o] = p;
                    g_ovf_tgt[o] = ts[k];
                    g_ovf_w[o] = ws[k];
                }
            }
        }
    }
}

// ---------------------------------------------------------------------------
// Persistent simulation. One thread per neuron; all state in registers.
__global__ void __launch_bounds__(TPB, 1) k_sim(
    const float* __restrict__ x_ext,
    float* __restrict__ out,
    const float* __restrict__ v0,
    const float* __restrict__ vth_,
    const float* __restrict__ vreset_,
    const float* __restrict__ tref_,
    const float* __restrict__ decay_,
    const float* __restrict__ cf_,
    const float* __restrict__ el_,
    const float* __restrict__ amps_,
    const float* __restrict__ ascd_,
    const float* __restrict__ syn_decay,
    const float* __restrict__ psc_init)
{
    __shared__ int q_ent[TPB];         // packed (n<<7 | m)
    __shared__ int q_n2[2];            // parity queue counters

    const int n = blockIdx.x * TPB + threadIdx.x;
    const bool act = (n < Nn);
    const int wid = threadIdx.x >> 5;
    const int lane = threadIdx.x & 31;

    const float4 sd = *(const float4*)syn_decay;
    const float4 pi = *(const float4*)psc_init;

    // Register-resident state.
    float v = 0.f, r = 0.f, z = 0.f;
    float2 a = make_float2(0.f, 0.f);
    float4 psc = make_float4(0.f, 0.f, 0.f, 0.f);
    float4 pr  = make_float4(0.f, 0.f, 0.f, 0.f);
    // Register-resident params.
    float vth = 1.f, inv_vth = 1.f, rst = 0.f, trf = 0.f;
    float dec = 0.f, cf = 0.f, el = 0.f;
    float2 am = make_float2(0.f, 0.f), ad = make_float2(0.f, 0.f);
    int sc = 0;
    float4 x = make_float4(0.f, 0.f, 0.f, 0.f);

    if (act) {
        v   = v0[n];
        vth = vth_[n];
        inv_vth = 1.f / vth;
        rst = vreset_[n] - vth;
        trf = tref_[n];
        dec = decay_[n];
        cf  = cf_[n];
        el  = el_[n];
        am  = *(const float2*)(&amps_[2 * n]);
        ad  = *(const float2*)(&ascd_[2 * n]);
        sc  = g_cnt[n];
        x   = __ldcs((const float4*)x_ext + n);   // step 0 input
    }
    const int m_syn = act ? ((sc < SS) ? sc : SS) : 0;
    const int my_pack = (n << 7) | m_syn;          // m_syn <= 64 fits 7 bits

    if (threadIdx.x == 0) { q_n2[0] = 0; q_n2[1] = 0; }
    __syncthreads();

    for (int t = 0; t < Tt; t++) {
        const int p = t & 1;
        float* rec_cur = g_rec[p];
        float* rec_nxt = g_rec[p ^ 1];

        float4 rec = make_float4(0.f, 0.f, 0.f, 0.f);
        float zn = 0.f;
        if (act) {
            // Issue the rec load NOW; its value is consumed only after the
            // publish+scatter phases (spike decision doesn't need it).
            rec = __ldcg((const float4*)(rec_cur + 4 * n));

            // ---- Spike decision: pure register math (no rec dependence). --
            // new_psc uses OLD psc and OLD psc_rise only.
            float4 npsc;
            npsc.x = psc.x * sd.x + sd.x * pr.x;
            npsc.y = psc.y * sd.y + sd.y * pr.y;
            npsc.z = psc.z * sd.z + sd.z * pr.z;
            npsc.w = psc.w * sd.w + sd.w * pr.w;

            float psum = ((npsc.x + npsc.y) + npsc.z) + npsc.w;
            float input_current = psum + (a.x + a.y);   // OLD asc

            float nv = dec * v + cf * (input_current + el) + z * rst;
            float vsc = (nv - vth) * inv_vth;

            zn = (vsc > 0.f) ? 1.f : 0.f;
            if (r > 0.f) zn = 0.f;

            // asc / refractory / state updates (z still old in asc).
            a.x = ad.x * a.x + z * am.x;
            a.y = ad.y * a.y + z * am.y;
            r = fmaxf(r - 1.f + zn * trf, 0.f);
            v = nv;
            psc = npsc;

            __stcs(&out[(size_t)t * Nn + n], zn);

            // Publish spike into the block scatter queue (packed entry).
            if (zn != 0.f) {
                int idx = atomicAdd(&q_n2[p], 1);
                q_ent[idx] = my_pack;
            }
            z = zn;
        }

        // Sync A: queue visible to all warps.
        __syncthreads();

        // Reset opposite-parity queue counter for step t+1.
        if (threadIdx.x == 0) q_n2[p ^ 1] = 0;

        // Block-cooperative scatter: warps round-robin over queue entries.
        {
            const int total = q_n2[p];
            for (int i = wid; i < total; i += NW) {
                int e = q_ent[i];
                int b = (e >> 7) * SS;
                int m = e & 127;
                for (int s = lane; s < m; s += 32) {
                    int2 rec2 = g_syn[b + s];
                    atomicAdd(&rec_nxt[rec2.x], __int_as_float(rec2.y));
                }
            }
            // Overflow entries (practically never taken).
            if (zn != 0.f && sc > SS) {
                int oc = g_ovf_cnt;
                if (oc > OVF_CAP) oc = OVF_CAP;
                for (int o = 0; o < oc; o++) {
                    if (g_ovf_pre[o] == n)
                        atomicAdd(&rec_nxt[g_ovf_tgt[o]], g_ovf_w[o]);
                }
            }
        }

        // ---- Consume rec (long since arrived): zero + psc_rise update. ----
        if (act) {
            if (rec.x != 0.f || rec.y != 0.f || rec.z != 0.f || rec.w != 0.f)
                __stcg((float4*)(rec_cur + 4 * n),
                       make_float4(0.f, 0.f, 0.f, 0.f));

            float in0 = rec.x + x.x;
            float in1 = rec.y + x.y;
            float in2 = rec.z + x.z;
            float in3 = rec.w + x.w;
            pr.x = pr.x * sd.x + in0 * pi.x;
            pr.y = pr.y * sd.y + in1 * pi.y;
            pr.z = pr.z * sd.z + in2 * pi.z;
            pr.w = pr.w * sd.w + in3 * pi.w;

            // Prefetch next step's external input (hidden behind the barrier).
            if (t + 1 < Tt)
                x = __ldcs((const float4*)x_ext + (size_t)(t + 1) * Nn + n);
        }

        // Grid barrier (skip after final step). Warps 1..21 signal completion
        // via non-blocking named-barrier arrive; warp 0 collects them, fires
        // the block's single global RED arrive, and polls.
        if (t + 1 < Tt) {
            if (wid != 0) {
                asm volatile("bar.arrive 1, %0;" :: "r"(TPB) : "memory");
            } else {
                asm volatile("bar.sync 1, %0;" :: "r"(TPB) : "memory");
                if (lane == 0) {
                    bar_arrive_release();      // release: block's scatters
                    const int target = GRID * (t + 1);
                    while (bar_read_acquire() < target) { }
                }
            }
            // Sync B: all warps wait for warp 0's poll to pass.
            __syncthreads();
        }
    }
}

// ---------------------------------------------------------------------------
extern "C" void kernel_launch(void* const* d_in, const int* in_sizes, int n_in,
                              void* d_out, int out_size) {
    const float* w_rec     = (const float*)d_in[0];
    const float* x_ext     = (const float*)d_in[1];
    const float* v0        = (const float*)d_in[2];
    const float* vth       = (const float*)d_in[3];
    const float* vreset    = (const float*)d_in[4];
    const float* tref      = (const float*)d_in[5];
    const float* decay     = (const float*)d_in[6];
    const float* cf        = (const float*)d_in[7];
    const float* el        = (const float*)d_in[8];
    const float* amps      = (const float*)d_in[9];
    const float* ascd      = (const float*)d_in[10];
    const float* syn_decay = (const float*)d_in[11];
    const float* psc_init  = (const float*)d_in[12];
    const int*   pre       = (const int*)d_in[13];
    const int*   post      = (const int*)d_in[14];
    const int*   rcp       = (const int*)d_in[15];
    float* out = (float*)d_out;

    k_zero<<<392, 256>>>();
    k_fill<<<(Ee / 8 + 255) / 256, 256>>>(pre, post, rcp, w_rec);
    k_sim<<<GRID, TPB>>>(x_ext, out, v0, vth, vreset, tref, decay, cf, el,
                         amps, ascd, syn_decay, psc_init);
}

// round 17
// speedup vs baseline: 35.1817x; 1.0796x over previous
#include <cuda_runtime.h>

// BillehColumn GLIF3 simulation, forward only.
// Round 17: R16 base (best @221.7us) with a SOFTWARE-PIPELINED grid barrier.
// The poll-wait for step t's barrier is deferred into step t+1, AFTER the
// (register-only) spike decision and queue publish — the barrier's spread +
// detect latency overlaps phase-1 compute instead of sitting serial at the
// end of each step. Queue bookkeeping becomes race-free under the deferred
// wait: per-step epoch counters (q_n[t], never reset) + parity-double-
// buffered entry array.

#define Nn 100000
#define Rr 4
#define Ee 2000000
#define Tt 50
#define NRr (Nn * Rr)
#define SS 64                 // synapse slots per pre-neuron
#define OVF_CAP 4096
#define TPB 704               // 22 warps
#define NW (TPB / 32)
#define GRID 148              // 148 x 704 = 104192 >= N, one block per SM

__device__ float g_rec[2][NRr];
__device__ int   g_cnt[Nn];
__device__ int   g_ovf_cnt;
__device__ int   g_bar;
__device__ int2  g_syn[Nn * SS];       // {target slot, weight bits}
__device__ int   g_ovf_pre[OVF_CAP];
__device__ int   g_ovf_tgt[OVF_CAP];
__device__ float g_ovf_w[OVF_CAP];

__device__ __forceinline__ void bar_arrive_release() {
    asm volatile("red.release.gpu.global.add.s32 [%0], 1;"
                 :: "l"(&g_bar) : "memory");
}
__device__ __forceinline__ int bar_read_acquire() {
    int v;
    asm volatile("ld.acquire.gpu.global.s32 %0, [%1];"
                 : "=r"(v) : "l"(&g_bar) : "memory");
    return v;
}

// ---------------------------------------------------------------------------
// Zero counts + scalars (rec zeroing lives in k_fill's prologue).
__global__ void k_zero() {
    int i = blockIdx.x * blockDim.x + threadIdx.x;
    int stride = gridDim.x * blockDim.x;
    for (int j = i; j < Nn; j += stride)
        g_cnt[j] = 0;
    if (i == 0) { g_ovf_cnt = 0; g_bar = 0; }
}

// ---------------------------------------------------------------------------
// Zero rec buffers, then single-pass synapse bucketing. 8 synapses/thread.
__global__ void k_fill(const int* __restrict__ pre,
                       const int* __restrict__ post,
                       const int* __restrict__ rcp,
                       const float* __restrict__ w) {
    int i = blockIdx.x * blockDim.x + threadIdx.x;   // octet index
    int nthreads = gridDim.x * blockDim.x;

    float4* r4 = (float4*)g_rec;
    for (int j = i; j < (2 * NRr) / 4; j += nthreads)
        r4[j] = make_float4(0.f, 0.f, 0.f, 0.f);

    if (i >= Ee / 8) return;

#pragma unroll
    for (int half = 0; half < 2; half++) {
        int q = 2 * i + half;                         // quad index
        int4 p4 = ((const int4*)pre)[q];
        int4 q4 = ((const int4*)post)[q];
        int4 r4i = ((const int4*)rcp)[q];
        float4 w4 = ((const float4*)w)[q];

        int   ps[4] = {p4.x, p4.y, p4.z, p4.w};
        int   ts[4] = {q4.x * Rr + r4i.x, q4.y * Rr + r4i.y,
                       q4.z * Rr + r4i.z, q4.w * Rr + r4i.w};
        float ws[4] = {w4.x, w4.y, w4.z, w4.w};

#pragma unroll
        for (int k = 0; k < 4; k++) {
            int p = ps[k];
            int c = atomicAdd(&g_cnt[p], 1);
            if (c < SS) {
                g_syn[p * SS + c] = make_int2(ts[k], __float_as_int(ws[k]));
            } else {
                int o = atomicAdd(&g_ovf_cnt, 1);
                if (o < OVF_CAP) {
                    g_ovf_pre[o] = p;
                    g_ovf_tgt[o] = ts[k];
                    g_ovf_w[o] = ws[k];
                }
            }
        }
    }
}

// ---------------------------------------------------------------------------
// Persistent simulation. One thread per neuron; all state in registers.
__global__ void __launch_bounds__(TPB, 1) k_sim(
    const float* __restrict__ x_ext,
    float* __restrict__ out,
    const float* __restrict__ v0,
    const float* __restrict__ vth_,
    const float* __restrict__ vreset_,
    const float* __restrict__ tref_,
    const float* __restrict__ decay_,
    const float* __restrict__ cf_,
    const float* __restrict__ el_,
    const float* __restrict__ amps_,
    const float* __restrict__ ascd_,
    const float* __restrict__ syn_decay,
    const float* __restrict__ psc_init)
{
    __shared__ int q_ent[2][TPB];      // parity-double-buffered packed entries
    __shared__ int q_n[Tt];            // per-step epoch counters (never reset)

    const int n = blockIdx.x * TPB + threadIdx.x;
    const bool act = (n < Nn);
    const int wid = threadIdx.x >> 5;
    const int lane = threadIdx.x & 31;

    const float4 sd = *(const float4*)syn_decay;
    const float4 pi = *(const float4*)psc_init;

    // Register-resident state.
    float v = 0.f, r = 0.f, z = 0.f;
    float2 a = make_float2(0.f, 0.f);
    float4 psc = make_float4(0.f, 0.f, 0.f, 0.f);
    float4 pr  = make_float4(0.f, 0.f, 0.f, 0.f);
    // Register-resident params.
    float vth = 1.f, inv_vth = 1.f, rst = 0.f, trf = 0.f;
    float dec = 0.f, cf = 0.f, el = 0.f;
    float2 am = make_float2(0.f, 0.f), ad = make_float2(0.f, 0.f);
    int sc = 0;
    float4 x = make_float4(0.f, 0.f, 0.f, 0.f);

    if (act) {
        v   = v0[n];
        vth = vth_[n];
        inv_vth = 1.f / vth;
        rst = vreset_[n] - vth;
        trf = tref_[n];
        dec = decay_[n];
        cf  = cf_[n];
        el  = el_[n];
        am  = *(const float2*)(&amps_[2 * n]);
        ad  = *(const float2*)(&ascd_[2 * n]);
        sc  = g_cnt[n];
        x   = __ldcs((const float4*)x_ext + n);   // step 0 input
    }
    const int m_syn = act ? ((sc < SS) ? sc : SS) : 0;
    const int my_pack = (n << 7) | m_syn;          // m_syn <= 64 fits 7 bits

    for (int i = threadIdx.x; i < Tt; i += TPB) q_n[i] = 0;
    __syncthreads();

    for (int t = 0; t < Tt; t++) {
        const int p = t & 1;
        float* rec_cur = g_rec[p];
        float* rec_nxt = g_rec[p ^ 1];

        // ---- Phase 1: spike decision — pure register math, needs nothing
        //      guarded by the pending grid barrier.
        float zn = 0.f;
        if (act) {
            float4 npsc;
            npsc.x = psc.x * sd.x + sd.x * pr.x;
            npsc.y = psc.y * sd.y + sd.y * pr.y;
            npsc.z = psc.z * sd.z + sd.z * pr.z;
            npsc.w = psc.w * sd.w + sd.w * pr.w;

            float psum = ((npsc.x + npsc.y) + npsc.z) + npsc.w;
            float input_current = psum + (a.x + a.y);   // OLD asc

            float nv = dec * v + cf * (input_current + el) + z * rst;
            float vsc = (nv - vth) * inv_vth;

            zn = (vsc > 0.f) ? 1.f : 0.f;
            if (r > 0.f) zn = 0.f;

            a.x = ad.x * a.x + z * am.x;
            a.y = ad.y * a.y + z * am.y;
            r = fmaxf(r - 1.f + zn * trf, 0.f);
            v = nv;
            psc = npsc;

            __stcs(&out[(size_t)t * Nn + n], zn);

            if (zn != 0.f) {
                int idx = atomicAdd(&q_n[t], 1);
                q_ent[p][idx] = my_pack;
            }
            z = zn;
        }

        // Sync A: queue entries visible block-wide.
        __syncthreads();

        // ---- Deferred grid wait: all blocks finished step t-1 (their
        //      scatters into g_rec[p] and zeroes of g_rec[p^1]).
        if (t > 0) {
            if (threadIdx.x == 0) {
                const int target = GRID * t;
                while (bar_read_acquire() < target) { }
            }
            __syncthreads();   // Sync B: wait observed block-wide
        }

        // ---- Phase 2: rec load (safe now; consumed after scatter). ----
        float4 rec = make_float4(0.f, 0.f, 0.f, 0.f);
        if (act)
            rec = __ldcg((const float4*)(rec_cur + 4 * n));

        // ---- Phase 3: block-cooperative scatter into rec_nxt. ----
        {
            const int total = q_n[t];
            for (int i = wid; i < total; i += NW) {
                int e = q_ent[p][i];
                int b = (e >> 7) * SS;
                int m = e & 127;
                for (int s = lane; s < m; s += 32) {
                    int2 rec2 = g_syn[b + s];
                    atomicAdd(&rec_nxt[rec2.x], __int_as_float(rec2.y));
                }
            }
            // Overflow entries (practically never taken).
            if (zn != 0.f && sc > SS) {
                int oc = g_ovf_cnt;
                if (oc > OVF_CAP) oc = OVF_CAP;
                for (int o = 0; o < oc; o++) {
                    if (g_ovf_pre[o] == n)
                        atomicAdd(&rec_nxt[g_ovf_tgt[o]], g_ovf_w[o]);
                }
            }
        }

        // ---- Phase 4: consume rec (arrived): zero + psc_rise update. ----
        if (act) {
            if (rec.x != 0.f || rec.y != 0.f || rec.z != 0.f || rec.w != 0.f)
                __stcg((float4*)(rec_cur + 4 * n),
                       make_float4(0.f, 0.f, 0.f, 0.f));

            float in0 = rec.x + x.x;
            float in1 = rec.y + x.y;
            float in2 = rec.z + x.z;
            float in3 = rec.w + x.w;
            pr.x = pr.x * sd.x + in0 * pi.x;
            pr.y = pr.y * sd.y + in1 * pi.y;
            pr.z = pr.z * sd.z + in2 * pi.z;
            pr.w = pr.w * sd.w + in3 * pi.w;

            // Prefetch next step's external input.
            if (t + 1 < Tt)
                x = __ldcs((const float4*)x_ext + (size_t)(t + 1) * Nn + n);
        }

        // ---- Completion arrive (no wait here — deferred to step t+1). ----
        if (t + 1 < Tt) {
            if (wid != 0) {
                asm volatile("bar.arrive 1, %0;" :: "r"(TPB) : "memory");
            } else {
                asm volatile("bar.sync 1, %0;" :: "r"(TPB) : "memory");
                if (lane == 0)
                    bar_arrive_release();   // release: block's scatters+zeroes
            }
        }
    }
}

// ---------------------------------------------------------------------------
extern "C" void kernel_launch(void* const* d_in, const int* in_sizes, int n_in,
                              void* d_out, int out_size) {
    const float* w_rec     = (const float*)d_in[0];
    const float* x_ext     = (const float*)d_in[1];
    const float* v0        = (const float*)d_in[2];
    const float* vth       = (const float*)d_in[3];
    const float* vreset    = (const float*)d_in[4];
    const float* tref      = (const float*)d_in[5];
    const float* decay     = (const float*)d_in[6];
    const float* cf        = (const float*)d_in[7];
    const float* el        = (const float*)d_in[8];
    const float* amps      = (const float*)d_in[9];
    const float* ascd      = (const float*)d_in[10];
    const float* syn_decay = (const float*)d_in[11];
    const float* psc_init  = (const float*)d_in[12];
    const int*   pre       = (const int*)d_in[13];
    const int*   post      = (const int*)d_in[14];
    const int*   rcp       = (const int*)d_in[15];
    float* out = (float*)d_out;

    k_zero<<<392, 256>>>();
    k_fill<<<(Ee / 8 + 255) / 256, 256>>>(pre, post, rcp, w_rec);
    k_sim<<<GRID, TPB>>>(x_ext, out, v0, vth, vreset, tref, decay, cf, el,
                         amps, ascd, syn_decay, psc_init);
}